// round 8
// baseline (speedup 1.0000x reference)
#include <cuda_runtime.h>
#include <cuda_bf16.h>
#include <math_constants.h>
#include <mma.h>

using namespace nvcuda;

#define BB 2
#define NN 2048
#define HH 8
#define DD 64
#define FIN 512
#define HD 512
#define EPS 1e-5f
#define SCALE 0.125f
#define NW (NN / 32)

// Device scratch
__device__ float g_h[BB * NN * HD];
__device__ float g_S[(size_t)BB * HH * NN * NN];       // unnormalized exp values
__device__ float g_O[BB * NN * HD];
__device__ float g_rowsum[BB * HH * NN];
__device__ unsigned g_mask[(size_t)BB * NN * NW];
// Fragment-order packed K/V tiles: per (bh, mtile) 2048 float2 (16 KB)
// g_hS: [bh][mt][r][q][kc]       pair {h[r][8kc+q], h[r][8kc+q+4]}
// g_hV: [bh][mt][kc][q][g][df]   pair {h[8kc+q][8df+g], h[8kc+q+4][8df+g]}
__device__ float4 g_hS[16 * 32 * 1024];
__device__ float4 g_hV[16 * 32 * 1024];

__device__ __forceinline__ float f2tf32(float x) {
    float r;
    asm("cvt.rna.tf32.f32 %0, %1;" : "=f"(r) : "f"(x));
    return r;
}

__device__ __forceinline__ void mma_tf32(float d[4], unsigned a0, unsigned a1,
                                         unsigned a2, unsigned a3,
                                         unsigned b0, unsigned b1) {
    asm volatile(
        "mma.sync.aligned.m16n8k8.row.col.f32.tf32.tf32.f32 "
        "{%0,%1,%2,%3}, {%4,%5,%6,%7}, {%8,%9}, {%0,%1,%2,%3};"
        : "+f"(d[0]), "+f"(d[1]), "+f"(d[2]), "+f"(d[3])
        : "r"(a0), "r"(a1), "r"(a2), "r"(a3), "r"(b0), "r"(b1));
}

// ---------------------------------------------------------------------------
// K0: pack adj -> bitmask
// ---------------------------------------------------------------------------
__global__ void k_pack(const int* __restrict__ adj) {
    const int row = blockIdx.x;
    const int t = threadIdx.x;
    const int warp = t >> 5, lane = t & 31;
    const int* arow = adj + (size_t)row * NN;
    #pragma unroll
    for (int j = warp; j < NW; j += 8) {
        unsigned bit = (arow[j * 32 + lane] != 0) ? 1u : 0u;
        unsigned word = __ballot_sync(0xffffffffu, bit);
        if (lane == 0) g_mask[(size_t)row * NW + j] = word;
    }
}

// ---------------------------------------------------------------------------
// K1: h = x @ W + b (tf32 wmma); writes g_h (tf32-rounded) + packed g_hS/g_hV
// ---------------------------------------------------------------------------
__global__ void k_proj(const float* __restrict__ x, const float* __restrict__ W,
                       const float* __restrict__ bias) {
    __shared__ float Xs[64][72];
    __shared__ float Ws[64][72];

    const int t = threadIdx.x;
    const int wid = t >> 5;
    const int warp_m = (wid & 1) * 32;
    const int warp_n = (wid >> 1) * 32;
    const int row0 = blockIdx.y * 64;
    const int col0 = blockIdx.x * 64;

    wmma::fragment<wmma::accumulator, 16, 16, 8, float> c[2][2];
    #pragma unroll
    for (int i = 0; i < 2; i++)
        #pragma unroll
        for (int j = 0; j < 2; j++) wmma::fill_fragment(c[i][j], 0.f);

    for (int k0 = 0; k0 < FIN; k0 += 64) {
        #pragma unroll
        for (int i = 0; i < 8; i++) {
            int idx = t + i * 128;
            int r = idx >> 4, c4 = idx & 15;
            float4 v = *(const float4*)&x[(size_t)(row0 + r) * FIN + k0 + c4 * 4];
            v.x = f2tf32(v.x); v.y = f2tf32(v.y); v.z = f2tf32(v.z); v.w = f2tf32(v.w);
            *(float4*)&Xs[r][c4 * 4] = v;
            float4 w = *(const float4*)&W[(size_t)(k0 + r) * HD + col0 + c4 * 4];
            w.x = f2tf32(w.x); w.y = f2tf32(w.y); w.z = f2tf32(w.z); w.w = f2tf32(w.w);
            *(float4*)&Ws[r][c4 * 4] = w;
        }
        __syncthreads();
        #pragma unroll
        for (int kk = 0; kk < 8; kk++) {
            wmma::fragment<wmma::matrix_a, 16, 16, 8, wmma::precision::tf32, wmma::row_major> a[2];
            wmma::fragment<wmma::matrix_b, 16, 16, 8, wmma::precision::tf32, wmma::row_major> bfr[2];
            #pragma unroll
            for (int i = 0; i < 2; i++)
                wmma::load_matrix_sync(a[i], &Xs[warp_m + 16 * i][kk * 8], 72);
            #pragma unroll
            for (int j = 0; j < 2; j++)
                wmma::load_matrix_sync(bfr[j], &Ws[kk * 8][warp_n + 16 * j], 72);
            #pragma unroll
            for (int i = 0; i < 2; i++)
                #pragma unroll
                for (int j = 0; j < 2; j++)
                    wmma::mma_sync(c[i][j], a[i], bfr[j], c[i][j]);
        }
        __syncthreads();
    }

    __shared__ float Stage[64][72];
    #pragma unroll
    for (int i = 0; i < 2; i++)
        #pragma unroll
        for (int j = 0; j < 2; j++)
            wmma::store_matrix_sync(&Stage[warp_m + 16 * i][warp_n + 16 * j], c[i][j], 72,
                                    wmma::mem_row_major);
    __syncthreads();

    // round Stage to tf32 in-place (so g_h, g_hS, g_hV are all consistent)
    #pragma unroll
    for (int i = 0; i < 8; i++) {
        int idx = t + i * 128;
        int r = idx >> 4, c4 = idx & 15;
        float4 v = *(float4*)&Stage[r][c4 * 4];
        float4 bb = *(const float4*)&bias[col0 + c4 * 4];
        v.x = f2tf32(v.x + bb.x); v.y = f2tf32(v.y + bb.y);
        v.z = f2tf32(v.z + bb.z); v.w = f2tf32(v.w + bb.w);
        *(float4*)&Stage[r][c4 * 4] = v;
        *(float4*)&g_h[(size_t)(row0 + r) * HD + col0 + c4 * 4] = v;
    }
    __syncthreads();

    // packed writes
    const int b = row0 >> 11;
    const int hh = col0 >> 6;
    const int mt = (row0 & (NN - 1)) >> 6;
    const size_t tb = ((size_t)(b * 8 + hh) * 32 + mt) * 1024;   // float4 units

    #pragma unroll
    for (int i = 0; i < 8; i++) {
        int c4 = t + i * 128;          // 0..1023
        int fidx = 2 * c4;
        {   // g_hS: [r][q][kc]
            int r = fidx >> 5, q = (fidx >> 3) & 3, kc = fidx & 7;
            float4 o;
            o.x = Stage[r][8 * kc + q];
            o.y = Stage[r][8 * kc + q + 4];
            o.z = Stage[r][8 * (kc + 1) + q];
            o.w = Stage[r][8 * (kc + 1) + q + 4];
            g_hS[tb + c4] = o;
        }
        {   // g_hV: [kc][q][g][df]
            int kc = fidx >> 8, q = (fidx >> 6) & 3, gg = (fidx >> 3) & 7, df = fidx & 7;
            float4 o;
            o.x = Stage[8 * kc + q][8 * df + gg];
            o.y = Stage[8 * kc + q + 4][8 * df + gg];
            o.z = Stage[8 * kc + q][8 * (df + 1) + gg];
            o.w = Stage[8 * kc + q + 4][8 * (df + 1) + gg];
            g_hV[tb + c4] = o;
        }
    }
}

// ---------------------------------------------------------------------------
// K2: register-resident fused attention, fragment-order packed tiles
// CTA: 256 threads / 8 warps; 128-row q-tile; 2 CTAs/SM.
// smem per buffer: SK 64*40 float2 + VP 8*328 float2
// ---------------------------------------------------------------------------
#define SK_R 40            // SK row stride (float2)
#define SK_Q 10            // SK q stride (float2)
#define VP_KC 328          // VP kc stride (float2)
#define VP_Q 82            // VP q stride (float2)
#define VP_G 10            // VP g stride (float2)
#define SKF2 (64 * SK_R)   // 2560
#define VPF2 (8 * VP_KC)   // 2624
#define BUF2 (SKF2 + VPF2) // 5184 float2 per buffer
#define SMEMB (2 * BUF2 * 8)   // 82944 bytes

__global__ __launch_bounds__(256, 2) void k_fused() {
    extern __shared__ float2 smb[];

    const int t = threadIdx.x;
    const int lane = t & 31;
    const int wid = t >> 5;
    const int g = lane >> 2;
    const int q = lane & 3;
    const int row0 = blockIdx.x * 128;
    const int bh = blockIdx.y;
    const int b = bh >> 3, hh = bh & 7;

    const float* Hb = g_h + (size_t)b * NN * HD + hh * DD;
    const int r_lo = row0 + wid * 16 + g;
    const int r_hi = r_lo + 8;

    // per-thread cp.async chunk offsets (float2 units), invariant across tiles
    int skoff[4], vpoff[4];
    #pragma unroll
    for (int k = 0; k < 4; k++) {
        int fidx = 2 * (t + k * 256);
        skoff[k] = (fidx >> 5) * SK_R + ((fidx >> 3) & 3) * SK_Q + (fidx & 7);
        vpoff[k] = (fidx >> 8) * VP_KC + ((fidx >> 6) & 3) * VP_Q +
                   ((fidx >> 3) & 7) * VP_G + (fidx & 7);
    }
    const float2* gS = (const float2*)&g_hS[(size_t)bh * 32 * 1024];
    const float2* gV = (const float2*)&g_hV[(size_t)bh * 32 * 1024];

    // prefetch tile 0
    {
        float2* base = smb;
        #pragma unroll
        for (int k = 0; k < 4; k++) {
            int c2 = 2 * (t + k * 256);
            unsigned ds = (unsigned)__cvta_generic_to_shared(&base[skoff[k]]);
            asm volatile("cp.async.ca.shared.global [%0], [%1], 16;" :: "r"(ds), "l"(&gS[c2]));
            unsigned dv = (unsigned)__cvta_generic_to_shared(&base[SKF2 + vpoff[k]]);
            asm volatile("cp.async.ca.shared.global [%0], [%1], 16;" :: "r"(dv), "l"(&gV[c2]));
        }
        asm volatile("cp.async.commit_group;");
    }

    // Q fragments (g_h pre-rounded to tf32)
    unsigned Qa[8][4];
    #pragma unroll
    for (int kc = 0; kc < 8; kc++) {
        Qa[kc][0] = __float_as_uint(Hb[(size_t)r_lo * HD + 8 * kc + q]);
        Qa[kc][1] = __float_as_uint(Hb[(size_t)r_hi * HD + 8 * kc + q]);
        Qa[kc][2] = __float_as_uint(Hb[(size_t)r_lo * HD + 8 * kc + q + 4]);
        Qa[kc][3] = __float_as_uint(Hb[(size_t)r_hi * HD + 8 * kc + q + 4]);
    }

    float Oa[8][4];
    #pragma unroll
    for (int f = 0; f < 8; f++)
        #pragma unroll
        for (int e = 0; e < 4; e++) Oa[f][e] = 0.f;
    float rs_lo = 0.f, rs_hi = 0.f;

    const unsigned* mrow_lo = &g_mask[((size_t)b * NN + r_lo) * NW];
    const unsigned* mrow_hi = &g_mask[((size_t)b * NN + r_hi) * NW];
    float* Srow_lo = &g_S[((size_t)bh * NN + r_lo) * NN];
    float* Srow_hi = &g_S[((size_t)bh * NN + r_hi) * NN];

    for (int it = 0; it < 32; it++) {
        const int m0 = it * 64;
        asm volatile("cp.async.wait_group 0;");
        __syncthreads();

        if (it < 31) {
            float2* nb = smb + ((it + 1) & 1) * BUF2;
            const size_t tile = (size_t)(it + 1) * 2048;
            #pragma unroll
            for (int k = 0; k < 4; k++) {
                int c2 = 2 * (t + k * 256);
                unsigned ds = (unsigned)__cvta_generic_to_shared(&nb[skoff[k]]);
                asm volatile("cp.async.ca.shared.global [%0], [%1], 16;"
                             :: "r"(ds), "l"(&gS[tile + c2]));
                unsigned dv = (unsigned)__cvta_generic_to_shared(&nb[SKF2 + vpoff[k]]);
                asm volatile("cp.async.ca.shared.global [%0], [%1], 16;"
                             :: "r"(dv), "l"(&gV[tile + c2]));
            }
            asm volatile("cp.async.commit_group;");
        }

        const float2* SK = smb + (it & 1) * BUF2;
        const float2* VP = SK + SKF2;

        const unsigned m00 = __ldg(&mrow_lo[it * 2]);
        const unsigned m01 = __ldg(&mrow_lo[it * 2 + 1]);
        const unsigned m10 = __ldg(&mrow_hi[it * 2]);
        const unsigned m11 = __ldg(&mrow_hi[it * 2 + 1]);

        // ---- S = Q K^T (B-fragments: 4x LDS.128 per f) ----
        float Sa[8][4];
        #pragma unroll
        for (int f = 0; f < 8; f++)
            #pragma unroll
            for (int e = 0; e < 4; e++) Sa[f][e] = 0.f;

        #pragma unroll
        for (int f = 0; f < 8; f++) {
            const float4* skp = (const float4*)&SK[(8 * f + g) * SK_R + q * SK_Q];
            float4 p0 = skp[0], p1 = skp[1], p2 = skp[2], p3 = skp[3];
            mma_tf32(Sa[f], Qa[0][0], Qa[0][1], Qa[0][2], Qa[0][3],
                     __float_as_uint(p0.x), __float_as_uint(p0.y));
            mma_tf32(Sa[f], Qa[1][0], Qa[1][1], Qa[1][2], Qa[1][3],
                     __float_as_uint(p0.z), __float_as_uint(p0.w));
            mma_tf32(Sa[f], Qa[2][0], Qa[2][1], Qa[2][2], Qa[2][3],
                     __float_as_uint(p1.x), __float_as_uint(p1.y));
            mma_tf32(Sa[f], Qa[3][0], Qa[3][1], Qa[3][2], Qa[3][3],
                     __float_as_uint(p1.z), __float_as_uint(p1.w));
            mma_tf32(Sa[f], Qa[4][0], Qa[4][1], Qa[4][2], Qa[4][3],
                     __float_as_uint(p2.x), __float_as_uint(p2.y));
            mma_tf32(Sa[f], Qa[5][0], Qa[5][1], Qa[5][2], Qa[5][3],
                     __float_as_uint(p2.z), __float_as_uint(p2.w));
            mma_tf32(Sa[f], Qa[6][0], Qa[6][1], Qa[6][2], Qa[6][3],
                     __float_as_uint(p3.x), __float_as_uint(p3.y));
            mma_tf32(Sa[f], Qa[7][0], Qa[7][1], Qa[7][2], Qa[7][3],
                     __float_as_uint(p3.z), __float_as_uint(p3.w));
        }

        // ---- mask + exp + rowsum + stream E ----
        #pragma unroll
        for (int f = 0; f < 8; f++) {
            const unsigned wlo = (f < 4) ? m00 : m01;
            const unsigned whi = (f < 4) ? m10 : m11;
            const int sh = (8 * f + 2 * q) & 31;
            float e0 = ((wlo >> sh) & 1u)       ? __expf(Sa[f][0] * SCALE) : 0.f;
            float e1 = ((wlo >> (sh + 1)) & 1u) ? __expf(Sa[f][1] * SCALE) : 0.f;
            float e2 = ((whi >> sh) & 1u)       ? __expf(Sa[f][2] * SCALE) : 0.f;
            float e3 = ((whi >> (sh + 1)) & 1u) ? __expf(Sa[f][3] * SCALE) : 0.f;
            rs_lo += e0 + e1;
            rs_hi += e2 + e3;
            Sa[f][0] = e0; Sa[f][1] = e1; Sa[f][2] = e2; Sa[f][3] = e3;
            __stcs((float2*)&Srow_lo[m0 + 8 * f + 2 * q], make_float2(e0, e1));
            __stcs((float2*)&Srow_hi[m0 + 8 * f + 2 * q], make_float2(e2, e3));
        }

        // ---- O += E V (B-fragments: 4x LDS.128 per kc) ----
        const int src1 = (lane & ~3) | (q >> 1);
        const int src2 = src1 + 2;
        const bool odd = q & 1;
        #pragma unroll
        for (int kc = 0; kc < 8; kc++) {
            float c0 = Sa[kc][0], c1 = Sa[kc][1], c2 = Sa[kc][2], c3 = Sa[kc][3];
            float v00 = __shfl_sync(0xffffffffu, c0, src1);
            float v01 = __shfl_sync(0xffffffffu, c1, src1);
            float v02 = __shfl_sync(0xffffffffu, c2, src1);
            float v03 = __shfl_sync(0xffffffffu, c3, src1);
            float v10 = __shfl_sync(0xffffffffu, c0, src2);
            float v11 = __shfl_sync(0xffffffffu, c1, src2);
            float v12 = __shfl_sync(0xffffffffu, c2, src2);
            float v13 = __shfl_sync(0xffffffffu, c3, src2);
            unsigned a0 = __float_as_uint(odd ? v01 : v00);
            unsigned a1 = __float_as_uint(odd ? v03 : v02);
            unsigned a2 = __float_as_uint(odd ? v11 : v10);
            unsigned a3 = __float_as_uint(odd ? v13 : v12);
            const float4* vpp = (const float4*)&VP[kc * VP_KC + q * VP_Q + g * VP_G];
            float4 w0 = vpp[0], w1 = vpp[1], w2 = vpp[2], w3 = vpp[3];
            mma_tf32(Oa[0], a0, a1, a2, a3, __float_as_uint(w0.x), __float_as_uint(w0.y));
            mma_tf32(Oa[1], a0, a1, a2, a3, __float_as_uint(w0.z), __float_as_uint(w0.w));
            mma_tf32(Oa[2], a0, a1, a2, a3, __float_as_uint(w1.x), __float_as_uint(w1.y));
            mma_tf32(Oa[3], a0, a1, a2, a3, __float_as_uint(w1.z), __float_as_uint(w1.w));
            mma_tf32(Oa[4], a0, a1, a2, a3, __float_as_uint(w2.x), __float_as_uint(w2.y));
            mma_tf32(Oa[5], a0, a1, a2, a3, __float_as_uint(w2.z), __float_as_uint(w2.w));
            mma_tf32(Oa[6], a0, a1, a2, a3, __float_as_uint(w3.x), __float_as_uint(w3.y));
            mma_tf32(Oa[7], a0, a1, a2, a3, __float_as_uint(w3.z), __float_as_uint(w3.w));
        }
    }

    // ---- epilogue ----
    rs_lo += __shfl_xor_sync(0xffffffffu, rs_lo, 1);
    rs_lo += __shfl_xor_sync(0xffffffffu, rs_lo, 2);
    rs_hi += __shfl_xor_sync(0xffffffffu, rs_hi, 1);
    rs_hi += __shfl_xor_sync(0xffffffffu, rs_hi, 2);
    if (q == 0) {
        g_rowsum[(size_t)bh * NN + r_lo] = rs_lo;
        g_rowsum[(size_t)bh * NN + r_hi] = rs_hi;
    }
    const float inv_lo = 1.f / rs_lo;
    const float inv_hi = 1.f / rs_hi;
    float* O_lo = &g_O[((size_t)b * NN + r_lo) * HD + hh * DD];
    float* O_hi = &g_O[((size_t)b * NN + r_hi) * HD + hh * DD];
    #pragma unroll
    for (int df = 0; df < 8; df++) {
        *(float2*)&O_lo[8 * df + 2 * q] = make_float2(Oa[df][0] * inv_lo, Oa[df][1] * inv_lo);
        *(float2*)&O_hi[8 * df + 2 * q] = make_float2(Oa[df][2] * inv_hi, Oa[df][3] * inv_hi);
    }
}

// ---------------------------------------------------------------------------
// K3: mean over heads of p = e / rowsum  -> out_mean
// ---------------------------------------------------------------------------
__global__ void k_mean(float* __restrict__ out_mean) {
    __shared__ float inv[HH];
    const int row = blockIdx.x;
    const int b = row >> 11;
    const int n = row & (NN - 1);
    const int t = threadIdx.x;

    if (t < HH) inv[t] = 0.125f / g_rowsum[(size_t)(b * HH + t) * NN + n];
    __syncthreads();

    float* mrow = out_mean + (size_t)row * NN;
    #pragma unroll
    for (int c4 = t; c4 < NN / 4; c4 += 256) {
        float4 acc = make_float4(0.f, 0.f, 0.f, 0.f);
        #pragma unroll
        for (int h = 0; h < HH; h++) {
            const float4 e4 = __ldcs((const float4*)&g_S[((size_t)(b * HH + h) * NN + n) * NN + c4 * 4]);
            float iv = inv[h];
            acc.x += e4.x * iv; acc.y += e4.y * iv;
            acc.z += e4.z * iv; acc.w += e4.w * iv;
        }
        *(float4*)&mrow[c4 * 4] = acc;
    }
}

// ---------------------------------------------------------------------------
// K5: LayerNorm -> out
// ---------------------------------------------------------------------------
__global__ void k_ln(const float* __restrict__ gamma, const float* __restrict__ beta,
                     float* __restrict__ out) {
    __shared__ float red[128];
    __shared__ float red2[128];

    const int row = blockIdx.x;
    const int t = threadIdx.x;
    const float* v = g_O + (size_t)row * HD;

    float s = 0.f, s2 = 0.f;
    float vals[4];
    #pragma unroll
    for (int i = 0; i < 4; i++) {
        vals[i] = v[t + i * 128];
        s += vals[i];
        s2 += vals[i] * vals[i];
    }
    red[t] = s; red2[t] = s2;
    __syncthreads();
    for (int st = 64; st > 0; st >>= 1) {
        if (t < st) { red[t] += red[t + st]; red2[t] += red2[t + st]; }
        __syncthreads();
    }
    const float mu = red[0] * (1.f / HD);
    const float var = red2[0] * (1.f / HD) - mu * mu;
    const float rstd = rsqrtf(var + EPS);

    float* orow = out + (size_t)row * HD;
    #pragma unroll
    for (int i = 0; i < 4; i++) {
        int c = t + i * 128;
        orow[c] = (vals[i] - mu) * rstd * gamma[c] + beta[c];
    }
}

// ---------------------------------------------------------------------------
extern "C" void kernel_launch(void* const* d_in, const int* in_sizes, int n_in,
                              void* d_out, int out_size) {
    const float* x     = (const float*)d_in[0];
    const int*   adj   = (const int*)d_in[1];
    const float* W_w   = (const float*)d_in[2];
    const float* W_b   = (const float*)d_in[3];
    const float* gamma = (const float*)d_in[4];
    const float* beta  = (const float*)d_in[5];
    float* out = (float*)d_out;
    float* out_mean = out + (size_t)BB * NN * HD;

    cudaFuncSetAttribute(k_fused, cudaFuncAttributeMaxDynamicSharedMemorySize, SMEMB);

    k_pack<<<BB * NN, 256>>>(adj);
    k_proj<<<dim3(HD / 64, (BB * NN) / 64), 128>>>(x, W_w, W_b);
    k_fused<<<dim3(NN / 128, BB * HH), 256, SMEMB>>>();
    k_mean<<<BB * NN, 256>>>(out_mean);
    k_ln<<<BB * NN, 128>>>(gamma, beta, out);
}

// round 10
// speedup vs baseline: 1.0967x; 1.0967x over previous
#include <cuda_runtime.h>
#include <cuda_bf16.h>
#include <cuda_fp16.h>
#include <math_constants.h>
#include <mma.h>

using namespace nvcuda;

#define BB 2
#define NN 2048
#define HH 8
#define DD 64
#define FIN 512
#define HD 512
#define EPS 1e-5f
#define SCALE 0.125f
#define BIAS14 9.7040605f   // 14*ln2: e = exp(s/8)*2^-14, exact power-of-2 scale
#define NW (NN / 32)

// Device scratch
__device__ float g_h[BB * NN * HD];
__device__ __half g_S[(size_t)BB * HH * NN * NN];      // scaled exp values (fp16)
__device__ float g_O[BB * NN * HD];
__device__ float g_rowsum[BB * HH * NN];
__device__ unsigned g_mask[(size_t)BB * NN * NW];

__device__ __forceinline__ float f2tf32(float x) {
    float r;
    asm("cvt.rna.tf32.f32 %0, %1;" : "=f"(r) : "f"(x));
    return r;
}

__device__ __forceinline__ void mma_tf32(float d[4], unsigned a0, unsigned a1,
                                         unsigned a2, unsigned a3,
                                         unsigned b0, unsigned b1) {
    asm volatile(
        "mma.sync.aligned.m16n8k8.row.col.f32.tf32.tf32.f32 "
        "{%0,%1,%2,%3}, {%4,%5,%6,%7}, {%8,%9}, {%0,%1,%2,%3};"
        : "+f"(d[0]), "+f"(d[1]), "+f"(d[2]), "+f"(d[3])
        : "r"(a0), "r"(a1), "r"(a2), "r"(a3), "r"(b0), "r"(b1));
}

// ---------------------------------------------------------------------------
// K0: pack adj -> bitmask
// ---------------------------------------------------------------------------
__global__ void k_pack(const int* __restrict__ adj) {
    const int row = blockIdx.x;
    const int t = threadIdx.x;
    const int warp = t >> 5, lane = t & 31;
    const int* arow = adj + (size_t)row * NN;
    #pragma unroll
    for (int j = warp; j < NW; j += 8) {
        unsigned bit = (arow[j * 32 + lane] != 0) ? 1u : 0u;
        unsigned word = __ballot_sync(0xffffffffu, bit);
        if (lane == 0) g_mask[(size_t)row * NW + j] = word;
    }
}

// ---------------------------------------------------------------------------
// K1: h = x @ W + b   (tf32 wmma); outputs rounded to tf32
// ---------------------------------------------------------------------------
__global__ void k_proj(const float* __restrict__ x, const float* __restrict__ W,
                       const float* __restrict__ bias) {
    __shared__ float Xs[64][72];
    __shared__ float Ws[64][72];

    const int t = threadIdx.x;
    const int wid = t >> 5;
    const int warp_m = (wid & 1) * 32;
    const int warp_n = (wid >> 1) * 32;
    const int row0 = blockIdx.y * 64;
    const int col0 = blockIdx.x * 64;

    wmma::fragment<wmma::accumulator, 16, 16, 8, float> c[2][2];
    #pragma unroll
    for (int i = 0; i < 2; i++)
        #pragma unroll
        for (int j = 0; j < 2; j++) wmma::fill_fragment(c[i][j], 0.f);

    for (int k0 = 0; k0 < FIN; k0 += 64) {
        #pragma unroll
        for (int i = 0; i < 8; i++) {
            int idx = t + i * 128;
            int r = idx >> 4, c4 = idx & 15;
            float4 v = *(const float4*)&x[(size_t)(row0 + r) * FIN + k0 + c4 * 4];
            v.x = f2tf32(v.x); v.y = f2tf32(v.y); v.z = f2tf32(v.z); v.w = f2tf32(v.w);
            *(float4*)&Xs[r][c4 * 4] = v;
            float4 w = *(const float4*)&W[(size_t)(k0 + r) * HD + col0 + c4 * 4];
            w.x = f2tf32(w.x); w.y = f2tf32(w.y); w.z = f2tf32(w.z); w.w = f2tf32(w.w);
            *(float4*)&Ws[r][c4 * 4] = w;
        }
        __syncthreads();
        #pragma unroll
        for (int kk = 0; kk < 8; kk++) {
            wmma::fragment<wmma::matrix_a, 16, 16, 8, wmma::precision::tf32, wmma::row_major> a[2];
            wmma::fragment<wmma::matrix_b, 16, 16, 8, wmma::precision::tf32, wmma::row_major> bfr[2];
            #pragma unroll
            for (int i = 0; i < 2; i++)
                wmma::load_matrix_sync(a[i], &Xs[warp_m + 16 * i][kk * 8], 72);
            #pragma unroll
            for (int j = 0; j < 2; j++)
                wmma::load_matrix_sync(bfr[j], &Ws[kk * 8][warp_n + 16 * j], 72);
            #pragma unroll
            for (int i = 0; i < 2; i++)
                #pragma unroll
                for (int j = 0; j < 2; j++)
                    wmma::mma_sync(c[i][j], a[i], bfr[j], c[i][j]);
        }
        __syncthreads();
    }

    __shared__ float Stage[64][72];
    #pragma unroll
    for (int i = 0; i < 2; i++)
        #pragma unroll
        for (int j = 0; j < 2; j++)
            wmma::store_matrix_sync(&Stage[warp_m + 16 * i][warp_n + 16 * j], c[i][j], 72,
                                    wmma::mem_row_major);
    __syncthreads();
    #pragma unroll
    for (int i = 0; i < 8; i++) {
        int idx = t + i * 128;
        int r = idx >> 4, c4 = idx & 15;
        float4 v = *(float4*)&Stage[r][c4 * 4];
        float4 bb = *(const float4*)&bias[col0 + c4 * 4];
        v.x = f2tf32(v.x + bb.x); v.y = f2tf32(v.y + bb.y);
        v.z = f2tf32(v.z + bb.z); v.w = f2tf32(v.w + bb.w);
        *(float4*)&g_h[(size_t)(row0 + r) * HD + col0 + c4 * 4] = v;
    }
}

// ---------------------------------------------------------------------------
// K2: register-resident fused attention (raw mma.sync tf32)
// CTA: 256 threads / 8 warps; 128-row q-tile; 2 CTAs/SM.
// E stored scaled (e = exp(s/8)*2^-14) as fp16.
// ---------------------------------------------------------------------------
#define KSTR 68   // smem tile stride (floats)

__global__ __launch_bounds__(256, 2) void k_fused() {
    __shared__ float buf[2][64 * KSTR];

    const int t = threadIdx.x;
    const int lane = t & 31;
    const int wid = t >> 5;                 // 0..7
    const int g = lane >> 2;                // 0..7
    const int q = lane & 3;                 // 0..3
    const int row0 = blockIdx.x * 128;
    const int bh = blockIdx.y;
    const int b = bh >> 3, hh = bh & 7;

    const float* Hb = g_h + (size_t)b * NN * HD + hh * DD;
    const int r_lo = row0 + wid * 16 + g;
    const int r_hi = r_lo + 8;

    // prefetch K/V tile 0 via cp.async (64 rows x 64 cols)
    {
        #pragma unroll
        for (int k = 0; k < 4; k++) {
            int c = t + k * 256;             // 0..1023
            int r = c >> 4, seg = c & 15;
            unsigned dst = (unsigned)__cvta_generic_to_shared(&buf[0][r * KSTR + seg * 4]);
            const float* src = &Hb[(size_t)r * HD + seg * 4];
            asm volatile("cp.async.ca.shared.global [%0], [%1], 16;" :: "r"(dst), "l"(src));
        }
        asm volatile("cp.async.commit_group;");
    }

    // Q fragments (g_h pre-rounded to tf32)
    unsigned Qa[8][4];
    #pragma unroll
    for (int kc = 0; kc < 8; kc++) {
        Qa[kc][0] = __float_as_uint(Hb[(size_t)r_lo * HD + 8 * kc + q]);
        Qa[kc][1] = __float_as_uint(Hb[(size_t)r_hi * HD + 8 * kc + q]);
        Qa[kc][2] = __float_as_uint(Hb[(size_t)r_lo * HD + 8 * kc + q + 4]);
        Qa[kc][3] = __float_as_uint(Hb[(size_t)r_hi * HD + 8 * kc + q + 4]);
    }

    float Oa[8][4];
    #pragma unroll
    for (int f = 0; f < 8; f++)
        #pragma unroll
        for (int e = 0; e < 4; e++) Oa[f][e] = 0.f;
    float rs_lo = 0.f, rs_hi = 0.f;

    const unsigned* mrow_lo = &g_mask[((size_t)b * NN + r_lo) * NW];
    const unsigned* mrow_hi = &g_mask[((size_t)b * NN + r_hi) * NW];
    __half* Srow_lo = &g_S[((size_t)bh * NN + r_lo) * NN];
    __half* Srow_hi = &g_S[((size_t)bh * NN + r_hi) * NN];

    for (int it = 0; it < 32; it++) {
        const int m0 = it * 64;
        asm volatile("cp.async.wait_group 0;");
        __syncthreads();

        if (it < 31) {
            #pragma unroll
            for (int k = 0; k < 4; k++) {
                int c = t + k * 256;
                int r = c >> 4, seg = c & 15;
                unsigned dst = (unsigned)__cvta_generic_to_shared(
                    &buf[(it + 1) & 1][r * KSTR + seg * 4]);
                const float* src = &Hb[(size_t)(m0 + 64 + r) * HD + seg * 4];
                asm volatile("cp.async.ca.shared.global [%0], [%1], 16;" :: "r"(dst), "l"(src));
            }
            asm volatile("cp.async.commit_group;");
        }

        const float* Kb = buf[it & 1];

        const unsigned m00 = __ldg(&mrow_lo[it * 2]);
        const unsigned m01 = __ldg(&mrow_lo[it * 2 + 1]);
        const unsigned m10 = __ldg(&mrow_hi[it * 2]);
        const unsigned m11 = __ldg(&mrow_hi[it * 2 + 1]);

        // ---- S = Q K^T ----
        float Sa[8][4];
        #pragma unroll
        for (int f = 0; f < 8; f++)
            #pragma unroll
            for (int e = 0; e < 4; e++) Sa[f][e] = 0.f;

        #pragma unroll
        for (int f = 0; f < 8; f++) {
            #pragma unroll
            for (int kc = 0; kc < 8; kc++) {
                unsigned b0 = __float_as_uint(Kb[(8 * f + g) * KSTR + 8 * kc + q]);
                unsigned b1 = __float_as_uint(Kb[(8 * f + g) * KSTR + 8 * kc + q + 4]);
                mma_tf32(Sa[f], Qa[kc][0], Qa[kc][1], Qa[kc][2], Qa[kc][3], b0, b1);
            }
        }

        // ---- mask + exp(s/8 - 14ln2) + rowsum + stream E (fp16) ----
        #pragma unroll
        for (int f = 0; f < 8; f++) {
            const unsigned wlo = (f < 4) ? m00 : m01;
            const unsigned whi = (f < 4) ? m10 : m11;
            const int sh = (8 * f + 2 * q) & 31;
            float e0 = ((wlo >> sh) & 1u)       ? __expf(fmaf(Sa[f][0], SCALE, -BIAS14)) : 0.f;
            float e1 = ((wlo >> (sh + 1)) & 1u) ? __expf(fmaf(Sa[f][1], SCALE, -BIAS14)) : 0.f;
            float e2 = ((whi >> sh) & 1u)       ? __expf(fmaf(Sa[f][2], SCALE, -BIAS14)) : 0.f;
            float e3 = ((whi >> (sh + 1)) & 1u) ? __expf(fmaf(Sa[f][3], SCALE, -BIAS14)) : 0.f;
            rs_lo += e0 + e1;
            rs_hi += e2 + e3;
            Sa[f][0] = e0; Sa[f][1] = e1; Sa[f][2] = e2; Sa[f][3] = e3;
            __stcs((__half2*)&Srow_lo[m0 + 8 * f + 2 * q],
                   __float22half2_rn(make_float2(e0, e1)));
            __stcs((__half2*)&Srow_hi[m0 + 8 * f + 2 * q],
                   __float22half2_rn(make_float2(e2, e3)));
        }

        // ---- O += E V  (A fragments from Sa via intra-quad shuffles) ----
        const int src1 = (lane & ~3) | (q >> 1);
        const int src2 = src1 + 2;
        const bool odd = q & 1;
        #pragma unroll
        for (int kc = 0; kc < 8; kc++) {
            float c0 = Sa[kc][0], c1 = Sa[kc][1], c2 = Sa[kc][2], c3 = Sa[kc][3];
            float v00 = __shfl_sync(0xffffffffu, c0, src1);
            float v01 = __shfl_sync(0xffffffffu, c1, src1);
            float v02 = __shfl_sync(0xffffffffu, c2, src1);
            float v03 = __shfl_sync(0xffffffffu, c3, src1);
            float v10 = __shfl_sync(0xffffffffu, c0, src2);
            float v11 = __shfl_sync(0xffffffffu, c1, src2);
            float v12 = __shfl_sync(0xffffffffu, c2, src2);
            float v13 = __shfl_sync(0xffffffffu, c3, src2);
            unsigned a0 = __float_as_uint(odd ? v01 : v00);
            unsigned a1 = __float_as_uint(odd ? v03 : v02);
            unsigned a2 = __float_as_uint(odd ? v11 : v10);
            unsigned a3 = __float_as_uint(odd ? v13 : v12);
            #pragma unroll
            for (int df = 0; df < 8; df++) {
                unsigned b0 = __float_as_uint(Kb[(8 * kc + q) * KSTR + 8 * df + g]);
                unsigned b1 = __float_as_uint(Kb[(8 * kc + q + 4) * KSTR + 8 * df + g]);
                mma_tf32(Oa[df], a0, a1, a2, a3, b0, b1);
            }
        }
    }

    // ---- epilogue ----
    rs_lo += __shfl_xor_sync(0xffffffffu, rs_lo, 1);
    rs_lo += __shfl_xor_sync(0xffffffffu, rs_lo, 2);
    rs_hi += __shfl_xor_sync(0xffffffffu, rs_hi, 1);
    rs_hi += __shfl_xor_sync(0xffffffffu, rs_hi, 2);
    if (q == 0) {
        g_rowsum[(size_t)bh * NN + r_lo] = rs_lo;
        g_rowsum[(size_t)bh * NN + r_hi] = rs_hi;
    }
    const float inv_lo = 1.f / rs_lo;
    const float inv_hi = 1.f / rs_hi;
    float* O_lo = &g_O[((size_t)b * NN + r_lo) * HD + hh * DD];
    float* O_hi = &g_O[((size_t)b * NN + r_hi) * HD + hh * DD];
    #pragma unroll
    for (int df = 0; df < 8; df++) {
        *(float2*)&O_lo[8 * df + 2 * q] = make_float2(Oa[df][0] * inv_lo, Oa[df][1] * inv_lo);
        *(float2*)&O_hi[8 * df + 2 * q] = make_float2(Oa[df][2] * inv_hi, Oa[df][3] * inv_hi);
    }
}

// ---------------------------------------------------------------------------
// K3: mean over heads of p = e / rowsum  -> out_mean  (fp16 E)
// ---------------------------------------------------------------------------
__global__ void k_mean(float* __restrict__ out_mean) {
    __shared__ float inv[HH];
    const int row = blockIdx.x;
    const int b = row >> 11;
    const int n = row & (NN - 1);
    const int t = threadIdx.x;

    if (t < HH) inv[t] = 0.125f / g_rowsum[(size_t)(b * HH + t) * NN + n];
    __syncthreads();

    float* mrow = out_mean + (size_t)row * NN;
    #pragma unroll
    for (int c4 = t; c4 < NN / 4; c4 += 256) {
        float4 acc = make_float4(0.f, 0.f, 0.f, 0.f);
        #pragma unroll
        for (int h = 0; h < HH; h++) {
            const __half2* ep = (const __half2*)&g_S[((size_t)(b * HH + h) * NN + n) * NN + c4 * 4];
            float2 lo = __half22float2(__ldcs(&ep[0]));
            float2 hi = __half22float2(__ldcs(&ep[1]));
            float iv = inv[h];
            acc.x += lo.x * iv; acc.y += lo.y * iv;
            acc.z += hi.x * iv; acc.w += hi.y * iv;
        }
        *(float4*)&mrow[c4 * 4] = acc;
    }
}

// ---------------------------------------------------------------------------
// K5: LayerNorm -> out
// ---------------------------------------------------------------------------
__global__ void k_ln(const float* __restrict__ gamma, const float* __restrict__ beta,
                     float* __restrict__ out) {
    __shared__ float red[128];
    __shared__ float red2[128];

    const int row = blockIdx.x;
    const int t = threadIdx.x;
    const float* v = g_O + (size_t)row * HD;

    float s = 0.f, s2 = 0.f;
    float vals[4];
    #pragma unroll
    for (int i = 0; i < 4; i++) {
        vals[i] = v[t + i * 128];
        s += vals[i];
        s2 += vals[i] * vals[i];
    }
    red[t] = s; red2[t] = s2;
    __syncthreads();
    for (int st = 64; st > 0; st >>= 1) {
        if (t < st) { red[t] += red[t + st]; red2[t] += red2[t + st]; }
        __syncthreads();
    }
    const float mu = red[0] * (1.f / HD);
    const float var = red2[0] * (1.f / HD) - mu * mu;
    const float rstd = rsqrtf(var + EPS);

    float* orow = out + (size_t)row * HD;
    #pragma unroll
    for (int i = 0; i < 4; i++) {
        int c = t + i * 128;
        orow[c] = (vals[i] - mu) * rstd * gamma[c] + beta[c];
    }
}

// ---------------------------------------------------------------------------
extern "C" void kernel_launch(void* const* d_in, const int* in_sizes, int n_in,
                              void* d_out, int out_size) {
    const float* x     = (const float*)d_in[0];
    const int*   adj   = (const int*)d_in[1];
    const float* W_w   = (const float*)d_in[2];
    const float* W_b   = (const float*)d_in[3];
    const float* gamma = (const float*)d_in[4];
    const float* beta  = (const float*)d_in[5];
    float* out = (float*)d_out;
    float* out_mean = out + (size_t)BB * NN * HD;

    k_pack<<<BB * NN, 256>>>(adj);
    k_proj<<<dim3(HD / 64, (BB * NN) / 64), 128>>>(x, W_w, W_b);
    k_fused<<<dim3(NN / 128, BB * HH), 256>>>();
    k_mean<<<BB * NN, 256>>>(out_mean);
    k_ln<<<BB * NN, 128>>>(gamma, beta, out);
}

// round 11
// speedup vs baseline: 1.4952x; 1.3633x over previous
#include <cuda_runtime.h>
#include <cuda_bf16.h>
#include <cuda_fp16.h>
#include <math_constants.h>
#include <mma.h>

using namespace nvcuda;

#define BB 2
#define NN 2048
#define HH 8
#define DD 64
#define FIN 512
#define HD 512
#define EPS 1e-5f
#define SCALE 0.125f
#define BIAS14 9.7040605f   // 14*ln2: e = exp(s/8)*2^-14 (exact power-of-2 scale)
#define NW (NN / 32)

// Device scratch
__device__ __half g_hh[BB * NN * HD];                  // projected features fp16 row-major
__device__ __half g_hhT[BB * HH * DD * NN];            // [b][h][d][n] fp16 (for V-phase)
__device__ __half g_S[(size_t)BB * HH * NN * NN];      // scaled exp values fp16
__device__ float g_O[BB * NN * HD];
__device__ float g_rowsum[BB * HH * NN];
__device__ unsigned g_mask[(size_t)BB * NN * NW];

__device__ __forceinline__ float f2tf32(float x) {
    float r;
    asm("cvt.rna.tf32.f32 %0, %1;" : "=f"(r) : "f"(x));
    return r;
}

__device__ __forceinline__ void mma_f16(float d[4], unsigned a0, unsigned a1,
                                        unsigned a2, unsigned a3,
                                        unsigned b0, unsigned b1) {
    asm volatile(
        "mma.sync.aligned.m16n8k16.row.col.f32.f16.f16.f32 "
        "{%0,%1,%2,%3}, {%4,%5,%6,%7}, {%8,%9}, {%0,%1,%2,%3};"
        : "+f"(d[0]), "+f"(d[1]), "+f"(d[2]), "+f"(d[3])
        : "r"(a0), "r"(a1), "r"(a2), "r"(a3), "r"(b0), "r"(b1));
}

// ---------------------------------------------------------------------------
// K0: pack adj -> bitmask
// ---------------------------------------------------------------------------
__global__ void k_pack(const int* __restrict__ adj) {
    const int row = blockIdx.x;
    const int t = threadIdx.x;
    const int warp = t >> 5, lane = t & 31;
    const int* arow = adj + (size_t)row * NN;
    #pragma unroll
    for (int j = warp; j < NW; j += 8) {
        unsigned bit = (arow[j * 32 + lane] != 0) ? 1u : 0u;
        unsigned word = __ballot_sync(0xffffffffu, bit);
        if (lane == 0) g_mask[(size_t)row * NW + j] = word;
    }
}

// ---------------------------------------------------------------------------
// K1: h = x @ W + b (tf32 wmma); writes fp16 g_hh + transposed g_hhT
// ---------------------------------------------------------------------------
__global__ void k_proj(const float* __restrict__ x, const float* __restrict__ W,
                       const float* __restrict__ bias) {
    __shared__ float Xs[64][72];
    __shared__ float Ws[64][72];

    const int t = threadIdx.x;
    const int wid = t >> 5;
    const int warp_m = (wid & 1) * 32;
    const int warp_n = (wid >> 1) * 32;
    const int row0 = blockIdx.y * 64;
    const int col0 = blockIdx.x * 64;

    wmma::fragment<wmma::accumulator, 16, 16, 8, float> c[2][2];
    #pragma unroll
    for (int i = 0; i < 2; i++)
        #pragma unroll
        for (int j = 0; j < 2; j++) wmma::fill_fragment(c[i][j], 0.f);

    for (int k0 = 0; k0 < FIN; k0 += 64) {
        #pragma unroll
        for (int i = 0; i < 8; i++) {
            int idx = t + i * 128;
            int r = idx >> 4, c4 = idx & 15;
            float4 v = *(const float4*)&x[(size_t)(row0 + r) * FIN + k0 + c4 * 4];
            v.x = f2tf32(v.x); v.y = f2tf32(v.y); v.z = f2tf32(v.z); v.w = f2tf32(v.w);
            *(float4*)&Xs[r][c4 * 4] = v;
            float4 w = *(const float4*)&W[(size_t)(k0 + r) * HD + col0 + c4 * 4];
            w.x = f2tf32(w.x); w.y = f2tf32(w.y); w.z = f2tf32(w.z); w.w = f2tf32(w.w);
            *(float4*)&Ws[r][c4 * 4] = w;
        }
        __syncthreads();
        #pragma unroll
        for (int kk = 0; kk < 8; kk++) {
            wmma::fragment<wmma::matrix_a, 16, 16, 8, wmma::precision::tf32, wmma::row_major> a[2];
            wmma::fragment<wmma::matrix_b, 16, 16, 8, wmma::precision::tf32, wmma::row_major> bfr[2];
            #pragma unroll
            for (int i = 0; i < 2; i++)
                wmma::load_matrix_sync(a[i], &Xs[warp_m + 16 * i][kk * 8], 72);
            #pragma unroll
            for (int j = 0; j < 2; j++)
                wmma::load_matrix_sync(bfr[j], &Ws[kk * 8][warp_n + 16 * j], 72);
            #pragma unroll
            for (int i = 0; i < 2; i++)
                #pragma unroll
                for (int j = 0; j < 2; j++)
                    wmma::mma_sync(c[i][j], a[i], bfr[j], c[i][j]);
        }
        __syncthreads();
    }

    __shared__ float Stage[64][72];
    #pragma unroll
    for (int i = 0; i < 2; i++)
        #pragma unroll
        for (int j = 0; j < 2; j++)
            wmma::store_matrix_sync(&Stage[warp_m + 16 * i][warp_n + 16 * j], c[i][j], 72,
                                    wmma::mem_row_major);
    __syncthreads();

    // bias + fp16 row-major write; keep biased fp32 in Stage for transpose pass
    #pragma unroll
    for (int i = 0; i < 8; i++) {
        int idx = t + i * 128;
        int r = idx >> 4, c4 = idx & 15;
        float4 v = *(float4*)&Stage[r][c4 * 4];
        float4 bb = *(const float4*)&bias[col0 + c4 * 4];
        v.x += bb.x; v.y += bb.y; v.z += bb.z; v.w += bb.w;
        *(float4*)&Stage[r][c4 * 4] = v;
        __half2 p0 = __float22half2_rn(make_float2(v.x, v.y));
        __half2 p1 = __float22half2_rn(make_float2(v.z, v.w));
        *(__half2*)&g_hh[(size_t)(row0 + r) * HD + col0 + c4 * 4] = p0;
        *(__half2*)&g_hh[(size_t)(row0 + r) * HD + col0 + c4 * 4 + 2] = p1;
    }
    __syncthreads();

    // transposed fp16 write: g_hhT[b][hh][d][n]
    const int b = row0 >> 11;
    const int n0 = row0 & (NN - 1);
    const int hh = col0 >> 6;
    #pragma unroll
    for (int i = 0; i < 8; i++) {
        int idx = t + i * 128;
        int dr = idx >> 4, nc = idx & 15;
        __half2 p0 = __float22half2_rn(make_float2(Stage[nc * 4 + 0][dr], Stage[nc * 4 + 1][dr]));
        __half2 p1 = __float22half2_rn(make_float2(Stage[nc * 4 + 2][dr], Stage[nc * 4 + 3][dr]));
        __half* dst = &g_hhT[((size_t)(b * HH + hh) * DD + dr) * NN + n0 + nc * 4];
        *(__half2*)&dst[0] = p0;
        *(__half2*)&dst[2] = p1;
    }
}

// ---------------------------------------------------------------------------
// K2: register-resident fused attention (mma.m16n8k16 fp16, fp32 accum)
// CTA: 256 threads / 8 warps; 128-row q-tile; 2 CTAs/SM.
// No shuffles: E half2 C-fragments are directly the AV-mma A-fragments.
// ---------------------------------------------------------------------------
#define STRH 72   // smem tile stride (halfs)

__global__ __launch_bounds__(256, 2) void k_fused() {
    __shared__ __half bufK[2][64 * STRH];
    __shared__ __half bufV[2][64 * STRH];   // transposed: [d][m]

    const int t = threadIdx.x;
    const int lane = t & 31;
    const int wid = t >> 5;
    const int g = lane >> 2;
    const int q = lane & 3;
    const int row0 = blockIdx.x * 128;
    const int bh = blockIdx.y;
    const int b = bh >> 3, hh = bh & 7;

    const __half* Hb = g_hh + (size_t)b * NN * HD + hh * DD;
    const __half* HTb = g_hhT + (size_t)bh * DD * NN;
    const int r_lo = row0 + wid * 16 + g;
    const int r_hi = r_lo + 8;

    // prefetch tile 0: K row-major 64x64 fp16 + V transposed 64x64 fp16
    {
        #pragma unroll
        for (int k = 0; k < 2; k++) {
            int c = t + k * 256;             // 0..511
            int r = c >> 3, seg = c & 7;
            unsigned dk = (unsigned)__cvta_generic_to_shared(&bufK[0][r * STRH + seg * 8]);
            asm volatile("cp.async.ca.shared.global [%0], [%1], 16;"
                         :: "r"(dk), "l"(&Hb[(size_t)r * HD + seg * 8]));
            unsigned dv = (unsigned)__cvta_generic_to_shared(&bufV[0][r * STRH + seg * 8]);
            asm volatile("cp.async.ca.shared.global [%0], [%1], 16;"
                         :: "r"(dv), "l"(&HTb[(size_t)r * NN + seg * 8]));
        }
        asm volatile("cp.async.commit_group;");
    }

    // Q fragments fp16 (half2 pairs)
    unsigned Qa[4][4];
    #pragma unroll
    for (int kc = 0; kc < 4; kc++) {
        Qa[kc][0] = *(const unsigned*)&Hb[(size_t)r_lo * HD + 16 * kc + 2 * q];
        Qa[kc][1] = *(const unsigned*)&Hb[(size_t)r_hi * HD + 16 * kc + 2 * q];
        Qa[kc][2] = *(const unsigned*)&Hb[(size_t)r_lo * HD + 16 * kc + 8 + 2 * q];
        Qa[kc][3] = *(const unsigned*)&Hb[(size_t)r_hi * HD + 16 * kc + 8 + 2 * q];
    }

    float Oa[8][4];
    #pragma unroll
    for (int f = 0; f < 8; f++)
        #pragma unroll
        for (int e = 0; e < 4; e++) Oa[f][e] = 0.f;
    float rs_lo = 0.f, rs_hi = 0.f;

    const unsigned* mrow_lo = &g_mask[((size_t)b * NN + r_lo) * NW];
    const unsigned* mrow_hi = &g_mask[((size_t)b * NN + r_hi) * NW];
    __half* Srow_lo = &g_S[((size_t)bh * NN + r_lo) * NN];
    __half* Srow_hi = &g_S[((size_t)bh * NN + r_hi) * NN];

    for (int it = 0; it < 32; it++) {
        const int m0 = it * 64;
        asm volatile("cp.async.wait_group 0;");
        __syncthreads();

        if (it < 31) {
            #pragma unroll
            for (int k = 0; k < 2; k++) {
                int c = t + k * 256;
                int r = c >> 3, seg = c & 7;
                unsigned dk = (unsigned)__cvta_generic_to_shared(
                    &bufK[(it + 1) & 1][r * STRH + seg * 8]);
                asm volatile("cp.async.ca.shared.global [%0], [%1], 16;"
                             :: "r"(dk), "l"(&Hb[(size_t)(m0 + 64 + r) * HD + seg * 8]));
                unsigned dv = (unsigned)__cvta_generic_to_shared(
                    &bufV[(it + 1) & 1][r * STRH + seg * 8]);
                asm volatile("cp.async.ca.shared.global [%0], [%1], 16;"
                             :: "r"(dv), "l"(&HTb[(size_t)r * NN + m0 + 64 + seg * 8]));
            }
            asm volatile("cp.async.commit_group;");
        }

        const __half* Kb = bufK[it & 1];
        const __half* Vb = bufV[it & 1];

        const unsigned m00 = __ldg(&mrow_lo[it * 2]);
        const unsigned m01 = __ldg(&mrow_lo[it * 2 + 1]);
        const unsigned m10 = __ldg(&mrow_hi[it * 2]);
        const unsigned m11 = __ldg(&mrow_hi[it * 2 + 1]);

        // ---- S = Q K^T  (32 mma, B = half2 LDS) ----
        float Sa[8][4];
        #pragma unroll
        for (int f = 0; f < 8; f++)
            #pragma unroll
            for (int e = 0; e < 4; e++) Sa[f][e] = 0.f;

        #pragma unroll
        for (int f = 0; f < 8; f++) {
            const unsigned* kr = (const unsigned*)&Kb[(8 * f + g) * STRH];
            #pragma unroll
            for (int kc = 0; kc < 4; kc++) {
                unsigned b0 = kr[8 * kc + q];
                unsigned b1 = kr[8 * kc + 4 + q];
                mma_f16(Sa[f], Qa[kc][0], Qa[kc][1], Qa[kc][2], Qa[kc][3], b0, b1);
            }
        }

        // ---- mask + exp(s/8 - 14ln2) + rowsum + pack half2 + stream E ----
        unsigned H01[8], H23[8];
        #pragma unroll
        for (int f = 0; f < 8; f++) {
            const unsigned wlo = (f < 4) ? m00 : m01;
            const unsigned whi = (f < 4) ? m10 : m11;
            const int sh = (8 * f + 2 * q) & 31;
            float e0 = ((wlo >> sh) & 1u)       ? __expf(fmaf(Sa[f][0], SCALE, -BIAS14)) : 0.f;
            float e1 = ((wlo >> (sh + 1)) & 1u) ? __expf(fmaf(Sa[f][1], SCALE, -BIAS14)) : 0.f;
            float e2 = ((whi >> sh) & 1u)       ? __expf(fmaf(Sa[f][2], SCALE, -BIAS14)) : 0.f;
            float e3 = ((whi >> (sh + 1)) & 1u) ? __expf(fmaf(Sa[f][3], SCALE, -BIAS14)) : 0.f;
            rs_lo += e0 + e1;
            rs_hi += e2 + e3;
            __half2 p01 = __float22half2_rn(make_float2(e0, e1));
            __half2 p23 = __float22half2_rn(make_float2(e2, e3));
            H01[f] = *(unsigned*)&p01;
            H23[f] = *(unsigned*)&p23;
            __stcs((__half2*)&Srow_lo[m0 + 8 * f + 2 * q], p01);
            __stcs((__half2*)&Srow_hi[m0 + 8 * f + 2 * q], p23);
        }

        // ---- O += E V  (32 mma; A = E half2 fragments, NO shuffles) ----
        #pragma unroll
        for (int df = 0; df < 8; df++) {
            const unsigned* vr = (const unsigned*)&Vb[(8 * df + g) * STRH];
            #pragma unroll
            for (int kk = 0; kk < 4; kk++) {
                unsigned b0 = vr[8 * kk + q];
                unsigned b1 = vr[8 * kk + 4 + q];
                mma_f16(Oa[df], H01[2 * kk], H23[2 * kk], H01[2 * kk + 1], H23[2 * kk + 1],
                        b0, b1);
            }
        }
    }

    // ---- epilogue ----
    rs_lo += __shfl_xor_sync(0xffffffffu, rs_lo, 1);
    rs_lo += __shfl_xor_sync(0xffffffffu, rs_lo, 2);
    rs_hi += __shfl_xor_sync(0xffffffffu, rs_hi, 1);
    rs_hi += __shfl_xor_sync(0xffffffffu, rs_hi, 2);
    if (q == 0) {
        g_rowsum[(size_t)bh * NN + r_lo] = rs_lo;
        g_rowsum[(size_t)bh * NN + r_hi] = rs_hi;
    }
    const float inv_lo = 1.f / rs_lo;
    const float inv_hi = 1.f / rs_hi;
    float* O_lo = &g_O[((size_t)b * NN + r_lo) * HD + hh * DD];
    float* O_hi = &g_O[((size_t)b * NN + r_hi) * HD + hh * DD];
    #pragma unroll
    for (int df = 0; df < 8; df++) {
        *(float2*)&O_lo[8 * df + 2 * q] = make_float2(Oa[df][0] * inv_lo, Oa[df][1] * inv_lo);
        *(float2*)&O_hi[8 * df + 2 * q] = make_float2(Oa[df][2] * inv_hi, Oa[df][3] * inv_hi);
    }
}

// ---------------------------------------------------------------------------
// K3: mean over heads of p = e / rowsum  -> out_mean  (fp16 E)
// ---------------------------------------------------------------------------
__global__ void k_mean(float* __restrict__ out_mean) {
    __shared__ float inv[HH];
    const int row = blockIdx.x;
    const int b = row >> 11;
    const int n = row & (NN - 1);
    const int t = threadIdx.x;

    if (t < HH) inv[t] = 0.125f / g_rowsum[(size_t)(b * HH + t) * NN + n];
    __syncthreads();

    float* mrow = out_mean + (size_t)row * NN;
    #pragma unroll
    for (int c4 = t; c4 < NN / 4; c4 += 256) {
        float4 acc = make_float4(0.f, 0.f, 0.f, 0.f);
        #pragma unroll
        for (int h = 0; h < HH; h++) {
            const __half2* ep = (const __half2*)&g_S[((size_t)(b * HH + h) * NN + n) * NN + c4 * 4];
            float2 lo = __half22float2(__ldcs(&ep[0]));
            float2 hi = __half22float2(__ldcs(&ep[1]));
            float iv = inv[h];
            acc.x += lo.x * iv; acc.y += lo.y * iv;
            acc.z += hi.x * iv; acc.w += hi.y * iv;
        }
        *(float4*)&mrow[c4 * 4] = acc;
    }
}

// ---------------------------------------------------------------------------
// K5: LayerNorm -> out
// ---------------------------------------------------------------------------
__global__ void k_ln(const float* __restrict__ gamma, const float* __restrict__ beta,
                     float* __restrict__ out) {
    __shared__ float red[128];
    __shared__ float red2[128];

    const int row = blockIdx.x;
    const int t = threadIdx.x;
    const float* v = g_O + (size_t)row * HD;

    float s = 0.f, s2 = 0.f;
    float vals[4];
    #pragma unroll
    for (int i = 0; i < 4; i++) {
        vals[i] = v[t + i * 128];
        s += vals[i];
        s2 += vals[i] * vals[i];
    }
    red[t] = s; red2[t] = s2;
    __syncthreads();
    for (int st = 64; st > 0; st >>= 1) {
        if (t < st) { red[t] += red[t + st]; red2[t] += red2[t + st]; }
        __syncthreads();
    }
    const float mu = red[0] * (1.f / HD);
    const float var = red2[0] * (1.f / HD) - mu * mu;
    const float rstd = rsqrtf(var + EPS);

    float* orow = out + (size_t)row * HD;
    #pragma unroll
    for (int i = 0; i < 4; i++) {
        int c = t + i * 128;
        orow[c] = (vals[i] - mu) * rstd * gamma[c] + beta[c];
    }
}

// ---------------------------------------------------------------------------
extern "C" void kernel_launch(void* const* d_in, const int* in_sizes, int n_in,
                              void* d_out, int out_size) {
    const float* x     = (const float*)d_in[0];
    const int*   adj   = (const int*)d_in[1];
    const float* W_w   = (const float*)d_in[2];
    const float* W_b   = (const float*)d_in[3];
    const float* gamma = (const float*)d_in[4];
    const float* beta  = (const float*)d_in[5];
    float* out = (float*)d_out;
    float* out_mean = out + (size_t)BB * NN * HD;

    k_pack<<<BB * NN, 256>>>(adj);
    k_proj<<<dim3(HD / 64, (BB * NN) / 64), 128>>>(x, W_w, W_b);
    k_fused<<<dim3(NN / 128, BB * HH), 256>>>();
    k_mean<<<BB * NN, 256>>>(out_mean);
    k_ln<<<BB * NN, 128>>>(gamma, beta, out);
}